// round 17
// baseline (speedup 1.0000x reference)
#include <cuda_runtime.h>
#include <cuda_bf16.h>
#include <cuda_fp16.h>
#include <math.h>
#include <stdint.h>

#define NN    50000
#define MPAD  50048        // 391 * 128
#define EE    800000
#define HEADS 4
#define HID   64
#define OUTC  40

// ---------------- scratch (static device globals; no allocations) ----------
__device__ __half g_h1h [(size_t)MPAD * 256];  // layer-1 linear output, fp16
__device__ __half g_out1h[(size_t)NN * 256];   // layer-1 GAT output after ELU, fp16
__device__ __half g_h2h [(size_t)NN * OUTC];   // layer-2 linear output, fp16
__device__ float g_alS1[NN * HEADS];
__device__ float g_alD1[NN * HEADS];
__device__ float g_alS2[NN];
__device__ float g_alD2[NN];
__device__ unsigned g_mS1[HEADS];              // global max of alS1 per head (flipped uint)
__device__ unsigned g_mS2;                     // global max of alS2
__device__ int   g_deg   [NN];
__device__ int   g_rowptr[NN + 1];
__device__ int   g_cursor[NN];
__device__ int   g_csrsrc[EE + NN];
// bf16x3 split of W1^T (B operand); A (x) is split in-kernel
__device__ __nv_bfloat16 g_bhi[256 * 256];     // W1^T  [N=256][K=256]
__device__ __nv_bfloat16 g_blo[256 * 256];

// ---------------- helpers ---------------------------------------------------
__device__ __forceinline__ unsigned fl_f2u(float f) {   // order-preserving float->uint
    unsigned u = __float_as_uint(f);
    return (u & 0x80000000u) ? ~u : (u | 0x80000000u);
}
__device__ __forceinline__ float fl_u2f(unsigned u) {
    return __uint_as_float((u & 0x80000000u) ? (u & 0x7fffffffu) : ~u);
}
__device__ __forceinline__ uint32_t smem_u32(const void* p) {
    uint32_t a;
    asm("{ .reg .u64 t; cvta.to.shared.u64 t, %1; cvt.u32.u64 %0, t; }" : "=r"(a) : "l"(p));
    return a;
}
__device__ __forceinline__ void ldsm4(uint32_t* r, uint32_t addr) {
    asm volatile("ldmatrix.sync.aligned.m8n8.x4.shared.b16 {%0,%1,%2,%3}, [%4];"
                 : "=r"(r[0]), "=r"(r[1]), "=r"(r[2]), "=r"(r[3]) : "r"(addr));
}
__device__ __forceinline__ void mma_bf16(float* c, const uint32_t* a, const uint32_t* b) {
    asm volatile(
        "mma.sync.aligned.m16n8k16.row.col.f32.bf16.bf16.f32 "
        "{%0,%1,%2,%3}, {%4,%5,%6,%7}, {%8,%9}, {%0,%1,%2,%3};"
        : "+f"(c[0]), "+f"(c[1]), "+f"(c[2]), "+f"(c[3])
        : "r"(a[0]), "r"(a[1]), "r"(a[2]), "r"(a[3]), "r"(b[0]), "r"(b[1]));
}
__device__ __forceinline__ uint32_t pack_bf2(__nv_bfloat16 a, __nv_bfloat16 b) {
    __nv_bfloat162 t; t.x = a; t.y = b;
    return *(uint32_t*)&t;
}
__device__ __forceinline__ uint32_t h2_bits(__half2 h) { return *(uint32_t*)&h; }

// ---------------- CSR build ------------------------------------------------
__global__ void zero_deg_kernel(int n) {
    int i = blockIdx.x * blockDim.x + threadIdx.x;
    if (i < n) g_deg[i] = 0;
}

__global__ void deg_kernel(const int* __restrict__ dstE, int E, int Etot) {
    int i = blockIdx.x * blockDim.x + threadIdx.x;
    if (i < Etot) {
        int d = (i < E) ? dstE[i] : (i - E);   // self-loop for i >= E
        atomicAdd(&g_deg[d], 1);
    }
}

__global__ void scan_kernel(int n) {
    __shared__ int sums[1024];
    int tid = threadIdx.x;
    int chunk = (n + 1023) / 1024;
    int start = tid * chunk;
    int end = min(start + chunk, n);
    int s = 0;
    for (int i = start; i < end; i++) s += g_deg[i];
    sums[tid] = s;
    __syncthreads();
    for (int off = 1; off < 1024; off <<= 1) {
        int v = (tid >= off) ? sums[tid - off] : 0;
        __syncthreads();
        sums[tid] += v;
        __syncthreads();
    }
    int base = (tid > 0) ? sums[tid - 1] : 0;
    for (int i = start; i < end; i++) {
        g_rowptr[i] = base;
        g_cursor[i] = base;
        base += g_deg[i];
    }
    if (tid == 1023) g_rowptr[n] = base;
}

__global__ void scatter_kernel(const int* __restrict__ srcE,
                               const int* __restrict__ dstE, int E, int Etot) {
    int i = blockIdx.x * blockDim.x + threadIdx.x;
    if (i < Etot) {
        int s, d;
        if (i < E) { s = srcE[i]; d = dstE[i]; }
        else       { s = d = i - E; }
        int p = atomicAdd(&g_cursor[d], 1);
        g_csrsrc[p] = s;
    }
}

// ---------------- W1 transpose + split (also resets global-max cells) -------
__global__ void convw_kernel(const float* __restrict__ W) {
    int i = blockIdx.x * blockDim.x + threadIdx.x;
    if (i < HEADS) g_mS1[i] = 0u;        // reset before mma1's atomicMax
    if (i == HEADS) g_mS2 = 0u;          // reset before gemm2's atomicMax
    if (i >= 256 * 256) return;
    int n = i >> 8, k = i & 255;
    float v = W[k * 256 + n];
    __nv_bfloat16 h = __float2bfloat16(v);
    g_bhi[i] = h;
    g_blo[i] = __float2bfloat16(v - __bfloat162float(h));
}

// ---------------- fused GEMM1 (mma.sync bf16x3) + x-split + al1 -------------
#define SROW 40
#define SM_AHI 0
#define SM_ALO (128 * SROW)
#define SM_BHI (2 * 128 * SROW)
#define SM_BLO (2 * 128 * SROW + 256 * SROW)
#define MMA1_SMEM ((2 * 128 * SROW + 2 * 256 * SROW) * 2)

__global__ void __launch_bounds__(512, 1) mma1_kernel(const float* __restrict__ X,
                                                      const float* __restrict__ as1,
                                                      const float* __restrict__ ad1,
                                                      int M) {
    extern __shared__ __nv_bfloat16 sm[];
    int tid = threadIdx.x;
    int lane = tid & 31, wid = tid >> 5;
    int warp_m = (wid & 3) * 32;
    int warp_n = (wid >> 2) * 64;      // == head * 64
    int rowBase = blockIdx.x * 128;

    uint32_t aHiB = smem_u32(sm + SM_AHI), aLoB = smem_u32(sm + SM_ALO);
    uint32_t bHiB = smem_u32(sm + SM_BHI), bLoB = smem_u32(sm + SM_BLO);

    float acc[2][8][4];
#pragma unroll
    for (int im = 0; im < 2; im++)
#pragma unroll
        for (int jn = 0; jn < 8; jn++)
#pragma unroll
            for (int q = 0; q < 4; q++) acc[im][jn][q] = 0.f;

    int ar = tid >> 2, acg = (tid & 3) << 3;
    float4 pA0, pA1;
    uint4 pBh[2], pBl[2];

    {
        int grow = rowBase + ar;
        if (grow < M) {
            pA0 = *(const float4*)(X + (size_t)grow * 256 + acg);
            pA1 = *(const float4*)(X + (size_t)grow * 256 + acg + 4);
        } else {
            pA0 = make_float4(0.f, 0.f, 0.f, 0.f);
            pA1 = pA0;
        }
#pragma unroll
        for (int l = 0; l < 2; l++) {
            int v = tid + (l << 9);
            int br = v >> 2, bcg = (v & 3) << 3;
            pBh[l] = *(const uint4*)(g_bhi + (size_t)br * 256 + bcg);
            pBl[l] = *(const uint4*)(g_blo + (size_t)br * 256 + bcg);
        }
    }

    for (int c = 0; c < 8; c++) {
        __syncthreads();
        {
            int so = ar * SROW + acg;
            float f[8] = {pA0.x, pA0.y, pA0.z, pA0.w, pA1.x, pA1.y, pA1.z, pA1.w};
            __nv_bfloat16 hi[8], lo[8];
#pragma unroll
            for (int t = 0; t < 8; t++) {
                hi[t] = __float2bfloat16(f[t]);
                lo[t] = __float2bfloat16(f[t] - __bfloat162float(hi[t]));
            }
            uint4 uh, ul;
            uh.x = pack_bf2(hi[0], hi[1]); uh.y = pack_bf2(hi[2], hi[3]);
            uh.z = pack_bf2(hi[4], hi[5]); uh.w = pack_bf2(hi[6], hi[7]);
            ul.x = pack_bf2(lo[0], lo[1]); ul.y = pack_bf2(lo[2], lo[3]);
            ul.z = pack_bf2(lo[4], lo[5]); ul.w = pack_bf2(lo[6], lo[7]);
            *(uint4*)(sm + SM_AHI + so) = uh;
            *(uint4*)(sm + SM_ALO + so) = ul;
        }
#pragma unroll
        for (int l = 0; l < 2; l++) {
            int v = tid + (l << 9);
            int br = v >> 2, bcg = (v & 3) << 3;
            int so = br * SROW + bcg;
            *(uint4*)(sm + SM_BHI + so) = pBh[l];
            *(uint4*)(sm + SM_BLO + so) = pBl[l];
        }
        __syncthreads();
        if (c < 7) {
            int kk = (c + 1) * 32;
            int grow = rowBase + ar;
            if (grow < M) {
                pA0 = *(const float4*)(X + (size_t)grow * 256 + kk + acg);
                pA1 = *(const float4*)(X + (size_t)grow * 256 + kk + acg + 4);
            } else {
                pA0 = make_float4(0.f, 0.f, 0.f, 0.f);
                pA1 = pA0;
            }
#pragma unroll
            for (int l = 0; l < 2; l++) {
                int v = tid + (l << 9);
                int br = v >> 2, bcg = (v & 3) << 3;
                pBh[l] = *(const uint4*)(g_bhi + (size_t)br * 256 + kk + bcg);
                pBl[l] = *(const uint4*)(g_blo + (size_t)br * 256 + kk + bcg);
            }
        }
#pragma unroll
        for (int ks = 0; ks < 2; ks++) {
            uint32_t fAh[2][4], fAl[2][4];
#pragma unroll
            for (int im = 0; im < 2; im++) {
                uint32_t off = ((warp_m + im * 16 + (lane & 15)) * SROW +
                                ks * 16 + (lane >> 4) * 8) * 2;
                ldsm4(fAh[im], aHiB + off);
                ldsm4(fAl[im], aLoB + off);
            }
#pragma unroll
            for (int j2 = 0; j2 < 4; j2++) {
                int s = lane >> 3;
                uint32_t off = ((warp_n + j2 * 16 + ((s >> 1) << 3) + (lane & 7)) * SROW +
                                ks * 16 + ((s & 1) << 3)) * 2;
                uint32_t th[4], tl[4];
                ldsm4(th, bHiB + off);
                ldsm4(tl, bLoB + off);
#pragma unroll
                for (int im = 0; im < 2; im++) {
                    mma_bf16(acc[im][j2 * 2],     fAh[im], th);
                    mma_bf16(acc[im][j2 * 2 + 1], fAh[im], th + 2);
                    mma_bf16(acc[im][j2 * 2],     fAh[im], tl);
                    mma_bf16(acc[im][j2 * 2 + 1], fAh[im], tl + 2);
                    mma_bf16(acc[im][j2 * 2],     fAl[im], th);
                    mma_bf16(acc[im][j2 * 2 + 1], fAl[im], th + 2);
                }
            }
        }
    }

    // ---- epilogue: fp16 h1 stores + fused al1 (per-head dot + global max) --
    int c0 = (lane & 3) * 2;
    float sv[4], dv[4];
#pragma unroll
    for (int t = 0; t < 4; t++) { sv[t] = 0.f; dv[t] = 0.f; }

#pragma unroll
    for (int im = 0; im < 2; im++) {
        int row0 = rowBase + warp_m + im * 16 + (lane >> 2);
#pragma unroll
        for (int jn = 0; jn < 8; jn++) {
            int col = warp_n + jn * 8 + c0;
            *(__half2*)(g_h1h + (size_t)row0 * 256 + col) =
                __floats2half2_rn(acc[im][jn][0], acc[im][jn][1]);
            *(__half2*)(g_h1h + (size_t)(row0 + 8) * 256 + col) =
                __floats2half2_rn(acc[im][jn][2], acc[im][jn][3]);
            float ws0 = __ldg(as1 + col), ws1 = __ldg(as1 + col + 1);
            float wd0 = __ldg(ad1 + col), wd1 = __ldg(ad1 + col + 1);
            sv[im * 2]     += acc[im][jn][0] * ws0 + acc[im][jn][1] * ws1;
            sv[im * 2 + 1] += acc[im][jn][2] * ws0 + acc[im][jn][3] * ws1;
            dv[im * 2]     += acc[im][jn][0] * wd0 + acc[im][jn][1] * wd1;
            dv[im * 2 + 1] += acc[im][jn][2] * wd0 + acc[im][jn][3] * wd1;
        }
    }
#pragma unroll
    for (int t = 0; t < 4; t++) {
#pragma unroll
        for (int o = 1; o < 4; o <<= 1) {
            sv[t] += __shfl_xor_sync(0xffffffffu, sv[t], o);
            dv[t] += __shfl_xor_sync(0xffffffffu, dv[t], o);
        }
    }
    int head = warp_n >> 6;
    if ((lane & 3) == 0) {
#pragma unroll
        for (int t = 0; t < 4; t++) {
            int row = rowBase + warp_m + (t >> 1) * 16 + (lane >> 2) + (t & 1) * 8;
            if (row < M) {
                g_alS1[row * HEADS + head] = sv[t];
                g_alD1[row * HEADS + head] = dv[t];
            }
        }
    }
    float mx = fmaxf(fmaxf(sv[0], sv[1]), fmaxf(sv[2], sv[3]));
#pragma unroll
    for (int o = 4; o < 32; o <<= 1) mx = fmaxf(mx, __shfl_xor_sync(0xffffffffu, mx, o));
    if (lane == 0) atomicMax(&g_mS1[head], fl_f2u(mx));
}

// ---------------- fused softmax + aggregation, layer 1 ---------------------
// ONE warp per node, all 4 heads. Lane owns 8 contiguous channels
// (head = lane>>3). Inner loop 2-way unrolled for MLP.
__global__ void __launch_bounds__(256) agg1_kernel(const float* __restrict__ b1, int N) {
    int n = blockIdx.x * 8 + (threadIdx.x >> 5);
    int lane = threadIdx.x & 31;
    if (n >= N) return;
    int start = g_rowptr[n], end = g_rowptr[n + 1];
    int myh = lane >> 3;

    float4 ad4 = *(const float4*)(g_alD1 + n * 4);
    float adv[4] = {ad4.x, ad4.y, ad4.z, ad4.w};
    float m4[4];
#pragma unroll
    for (int h = 0; h < 4; h++) {
        float mg = fl_u2f(g_mS1[h]) + adv[h];
        m4[h] = (mg > 0.f) ? mg : 0.2f * mg;
    }

    __shared__ float4 sw_w[8][32];
    __shared__ int    sw_s[8][32];
    int w = threadIdx.x >> 5;
    float acc[8];
#pragma unroll
    for (int t = 0; t < 8; t++) acc[t] = 0.f;
    float sum0 = 0.f, sum1 = 0.f, sum2 = 0.f, sum3 = 0.f;

    for (int base = start; base < end; base += 32) {
        int cnt = min(32, end - base);
        if (lane < cnt) {
            int s = g_csrsrc[base + lane];
            float4 as4 = *(const float4*)(g_alS1 + s * 4);
            float v0 = as4.x + adv[0]; v0 = (v0 > 0.f) ? v0 : 0.2f * v0;
            float v1 = as4.y + adv[1]; v1 = (v1 > 0.f) ? v1 : 0.2f * v1;
            float v2 = as4.z + adv[2]; v2 = (v2 > 0.f) ? v2 : 0.2f * v2;
            float v3 = as4.w + adv[3]; v3 = (v3 > 0.f) ? v3 : 0.2f * v3;
            float w0 = __expf(v0 - m4[0]);
            float w1 = __expf(v1 - m4[1]);
            float w2 = __expf(v2 - m4[2]);
            float w3 = __expf(v3 - m4[3]);
            sw_w[w][lane] = make_float4(w0, w1, w2, w3);
            sw_s[w][lane] = s;
            sum0 += w0; sum1 += w1; sum2 += w2; sum3 += w3;
        }
        __syncwarp();
        int j = 0;
        for (; j + 2 <= cnt; j += 2) {
            float aw0 = ((const float*)&sw_w[w][j])[myh];
            float aw1 = ((const float*)&sw_w[w][j + 1])[myh];
            uint4 hv0 = *(const uint4*)(g_h1h + (size_t)sw_s[w][j]     * 256 + 8 * lane);
            uint4 hv1 = *(const uint4*)(g_h1h + (size_t)sw_s[w][j + 1] * 256 + 8 * lane);
            float2 a0 = __half22float2(*(const __half2*)&hv0.x);
            float2 a1 = __half22float2(*(const __half2*)&hv0.y);
            float2 a2 = __half22float2(*(const __half2*)&hv0.z);
            float2 a3 = __half22float2(*(const __half2*)&hv0.w);
            acc[0] += aw0 * a0.x; acc[1] += aw0 * a0.y;
            acc[2] += aw0 * a1.x; acc[3] += aw0 * a1.y;
            acc[4] += aw0 * a2.x; acc[5] += aw0 * a2.y;
            acc[6] += aw0 * a3.x; acc[7] += aw0 * a3.y;
            float2 c0 = __half22float2(*(const __half2*)&hv1.x);
            float2 c1 = __half22float2(*(const __half2*)&hv1.y);
            float2 c2 = __half22float2(*(const __half2*)&hv1.z);
            float2 c3 = __half22float2(*(const __half2*)&hv1.w);
            acc[0] += aw1 * c0.x; acc[1] += aw1 * c0.y;
            acc[2] += aw1 * c1.x; acc[3] += aw1 * c1.y;
            acc[4] += aw1 * c2.x; acc[5] += aw1 * c2.y;
            acc[6] += aw1 * c3.x; acc[7] += aw1 * c3.y;
        }
        if (j < cnt) {
            float aw = ((const float*)&sw_w[w][j])[myh];
            uint4 hv = *(const uint4*)(g_h1h + (size_t)sw_s[w][j] * 256 + 8 * lane);
            float2 f0 = __half22float2(*(const __half2*)&hv.x);
            float2 f1 = __half22float2(*(const __half2*)&hv.y);
            float2 f2 = __half22float2(*(const __half2*)&hv.z);
            float2 f3 = __half22float2(*(const __half2*)&hv.w);
            acc[0] += aw * f0.x; acc[1] += aw * f0.y;
            acc[2] += aw * f1.x; acc[3] += aw * f1.y;
            acc[4] += aw * f2.x; acc[5] += aw * f2.y;
            acc[6] += aw * f3.x; acc[7] += aw * f3.y;
        }
        __syncwarp();
    }
#pragma unroll
    for (int o = 16; o; o >>= 1) {
        sum0 += __shfl_xor_sync(0xffffffffu, sum0, o);
        sum1 += __shfl_xor_sync(0xffffffffu, sum1, o);
        sum2 += __shfl_xor_sync(0xffffffffu, sum2, o);
        sum3 += __shfl_xor_sync(0xffffffffu, sum3, o);
    }
    float sums[4] = {sum0, sum1, sum2, sum3};
    float inv = 1.0f / (sums[myh] + 1e-16f);

    float4 bA = *(const float4*)(b1 + 8 * lane);
    float4 bB = *(const float4*)(b1 + 8 * lane + 4);
    float r[8];
    r[0] = acc[0] * inv + bA.x; r[1] = acc[1] * inv + bA.y;
    r[2] = acc[2] * inv + bA.z; r[3] = acc[3] * inv + bA.w;
    r[4] = acc[4] * inv + bB.x; r[5] = acc[5] * inv + bB.y;
    r[6] = acc[6] * inv + bB.z; r[7] = acc[7] * inv + bB.w;
#pragma unroll
    for (int t = 0; t < 8; t++) r[t] = (r[t] > 0.f) ? r[t] : expm1f(r[t]);
    uint4 o;
    o.x = h2_bits(__floats2half2_rn(r[0], r[1]));
    o.y = h2_bits(__floats2half2_rn(r[2], r[3]));
    o.z = h2_bits(__floats2half2_rn(r[4], r[5]));
    o.w = h2_bits(__floats2half2_rn(r[6], r[7]));
    *(uint4*)(g_out1h + (size_t)n * 256 + 8 * lane) = o;
}

// ---------------- GEMM2 (fp16 in) + fused layer-2 logits + global max ------
__global__ void __launch_bounds__(256) gemm2_kernel(const float* __restrict__ W,
                                                    const float* __restrict__ as2,
                                                    const float* __restrict__ ad2, int M) {
    __shared__ float Ws[256 * OUTC];  // 40 KB
    int tid = threadIdx.x;
    for (int i = tid; i < (256 * OUTC) / 4; i += 256)
        *(float4*)&Ws[i * 4] = *(const float4*)(W + i * 4);
    __syncthreads();

    int r = tid >> 3;
    int g = tid & 7;
    int grow = blockIdx.x * 32 + r;
    if (grow >= M) return;

    float acc[5] = {0.f, 0.f, 0.f, 0.f, 0.f};
    const uint4* ap = (const uint4*)(g_out1h + (size_t)grow * 256);  // 8 halves each
#pragma unroll 4
    for (int k8 = 0; k8 < 32; k8++) {
        uint4 u = __ldg(&ap[k8]);
        float2 f0 = __half22float2(*(const __half2*)&u.x);
        float2 f1 = __half22float2(*(const __half2*)&u.y);
        float2 f2 = __half22float2(*(const __half2*)&u.z);
        float2 f3 = __half22float2(*(const __half2*)&u.w);
        float av[8] = {f0.x, f0.y, f1.x, f1.y, f2.x, f2.y, f3.x, f3.y};
#pragma unroll
        for (int q = 0; q < 8; q++) {
            const float* wrow = &Ws[(k8 * 8 + q) * OUTC + g * 5];
#pragma unroll
            for (int j = 0; j < 5; j++) acc[j] += av[q] * wrow[j];
        }
    }
    float s = 0.f, d = 0.f;
#pragma unroll
    for (int j = 0; j < 5; j++) {
        g_h2h[(size_t)grow * OUTC + g * 5 + j] = __float2half_rn(acc[j]);
        s += acc[j] * __ldg(as2 + g * 5 + j);
        d += acc[j] * __ldg(ad2 + g * 5 + j);
    }
#pragma unroll
    for (int o = 4; o; o >>= 1) {
        s += __shfl_xor_sync(0xffffffffu, s, o);
        d += __shfl_xor_sync(0xffffffffu, d, o);
    }
    if (g == 0) {
        g_alS2[grow] = s;
        g_alD2[grow] = d;
    }
    __shared__ float smax[256];
    smax[tid] = s;
    __syncthreads();
    for (int o = 128; o; o >>= 1) {
        if (tid < o) smax[tid] = fmaxf(smax[tid], smax[tid + o]);
        __syncthreads();
    }
    if (tid == 0) atomicMax(&g_mS2, fl_f2u(smax[0]));
}

// ---------------- fused softmax + aggregation, layer 2 ---------------------
// ONE warp per node; edge-parallel: 2 edges x 16 lanes, active lane loads
// uint2 (4 halves). Cross-edge reduce = shfl_xor(16). Coalesced float4 out.
__global__ void __launch_bounds__(256) agg2_kernel(const float* __restrict__ b2,
                                                   float* __restrict__ out, int N) {
    int n = blockIdx.x * 8 + (threadIdx.x >> 5);
    int lane = threadIdx.x & 31;
    if (n >= N) return;
    int start = g_rowptr[n], end = g_rowptr[n + 1];
    float ad = g_alD2[n];
    float mg = fl_u2f(g_mS2) + ad;
    float m = (mg > 0.f) ? mg : 0.2f * mg;

    int e = lane >> 4;          // edge sub-index 0/1
    int cl = lane & 15;         // channel chunk; active if cl < 10

    __shared__ float sw_w[8][32];
    __shared__ int   sw_s[8][32];
    int w = threadIdx.x >> 5;
    float acc0 = 0.f, acc1 = 0.f, acc2 = 0.f, acc3 = 0.f;
    float ssum = 0.f;
    bool act = (cl < 10);
    for (int base = start; base < end; base += 32) {
        int cnt = min(32, end - base);
        float wv = 0.f;
        if (lane < cnt) {
            int s = g_csrsrc[base + lane];
            float v = g_alS2[s] + ad;
            v = (v > 0.f) ? v : 0.2f * v;
            wv = __expf(v - m);
            sw_w[w][lane] = wv;
            sw_s[w][lane] = s;
        }
        ssum += wv;
        __syncwarp();
        for (int jb = 0; jb < cnt; jb += 2) {
            int j = jb + e;
            if (j < cnt && act) {
                float aw = sw_w[w][j];
                uint2 hv = *(const uint2*)(g_h2h + (size_t)sw_s[w][j] * OUTC + 4 * cl);
                float2 f0 = __half22float2(*(const __half2*)&hv.x);
                float2 f1 = __half22float2(*(const __half2*)&hv.y);
                acc0 += aw * f0.x; acc1 += aw * f0.y;
                acc2 += aw * f1.x; acc3 += aw * f1.y;
            }
        }
        __syncwarp();
    }
#pragma unroll
    for (int o = 16; o; o >>= 1) ssum += __shfl_xor_sync(0xffffffffu, ssum, o);
    // combine the two edge sub-accumulators (lane <-> lane^16)
    acc0 += __shfl_xor_sync(0xffffffffu, acc0, 16);
    acc1 += __shfl_xor_sync(0xffffffffu, acc1, 16);
    acc2 += __shfl_xor_sync(0xffffffffu, acc2, 16);
    acc3 += __shfl_xor_sync(0xffffffffu, acc3, 16);
    float inv = 1.0f / (ssum + 1e-16f);
    if (lane < 10) {
        float4 bv = *(const float4*)(b2 + 4 * lane);
        float4 o4 = make_float4(acc0 * inv + bv.x, acc1 * inv + bv.y,
                                acc2 * inv + bv.z, acc3 * inv + bv.w);
        *(float4*)(out + (size_t)n * OUTC + 4 * lane) = o4;
    }
}

// ---------------- launch ----------------------------------------------------
extern "C" void kernel_launch(void* const* d_in, const int* in_sizes, int n_in,
                              void* d_out, int out_size) {
    const float* x      = (const float*)d_in[0];
    const int*   ei     = (const int*)d_in[1];
    const float* W1     = (const float*)d_in[2];
    const float* a_src1 = (const float*)d_in[3];
    const float* a_dst1 = (const float*)d_in[4];
    const float* b1     = (const float*)d_in[5];
    const float* W2     = (const float*)d_in[6];
    const float* a_src2 = (const float*)d_in[7];
    const float* a_dst2 = (const float*)d_in[8];
    const float* b2     = (const float*)d_in[9];
    float* out = (float*)d_out;

    int N = in_sizes[0] / 256;   // 50000
    int E = in_sizes[1] / 2;     // 800000
    int Etot = E + N;
    const int* srcE = ei;
    const int* dstE = ei + E;

    // one-time resources (no device memory): side stream, events, smem opt-in
    static cudaStream_t sCsr = nullptr;
    static cudaEvent_t evRoot = nullptr, evCsr = nullptr;
    if (sCsr == nullptr) {
        cudaStreamCreateWithFlags(&sCsr, cudaStreamNonBlocking);
        cudaEventCreateWithFlags(&evRoot, cudaEventDisableTiming);
        cudaEventCreateWithFlags(&evCsr, cudaEventDisableTiming);
        cudaFuncSetAttribute(mma1_kernel,
                             cudaFuncAttributeMaxDynamicSharedMemorySize, MMA1_SMEM);
    }

    // fork: CSR build on side stream
    cudaEventRecord(evRoot, 0);
    cudaStreamWaitEvent(sCsr, evRoot, 0);
    zero_deg_kernel<<<(N + 255) / 256, 256, 0, sCsr>>>(N);
    deg_kernel<<<(Etot + 255) / 256, 256, 0, sCsr>>>(dstE, E, Etot);
    scan_kernel<<<1, 1024, 0, sCsr>>>(N);
    scatter_kernel<<<(Etot + 255) / 256, 256, 0, sCsr>>>(srcE, dstE, E, Etot);
    cudaEventRecord(evCsr, sCsr);

    // main stream: fused layer-1 linear chain
    convw_kernel<<<(256 * 256 + 255) / 256, 256>>>(W1);
    mma1_kernel<<<MPAD / 128, 512, MMA1_SMEM>>>(x, a_src1, a_dst1, N);

    // join: aggregation needs both chains
    cudaStreamWaitEvent(0, evCsr, 0);
    agg1_kernel<<<(N + 7) / 8, 256>>>(b1, N);

    // layer 2
    gemm2_kernel<<<(N + 31) / 32, 256>>>(W2, a_src2, a_dst2, N);
    agg2_kernel<<<(N + 7) / 8, 256>>>(b2, out, N);
}